// round 9
// baseline (speedup 1.0000x reference)
#include <cuda_runtime.h>
#include <cuda_bf16.h>
#include <cstdint>

// ---------------------------------------------------------------------------
// ConditionalRealNVP log_prob — R8: FP8 (e4m3) mma.sync m16n8k32 for GEMM1/2.
//   - W1,W2 stored x32 in fp8 (dodges e4m3 subnormals); hid1 stored x16.
//     Descale 1/32, 1/512 folded into the bias FMA of each epilogue.
//   - fp8 operands use NON-trans ldmatrix from byte-major [n][k]/[m][k] smem.
//   - Hidden-dim permutation pi on W2 rows makes the fp8 A-fragment repack
//     from C fragments a pure in-register cvt+mov.
//   - GEMM3 + hid2 stay bf16. h pre-converted to fp8 once (pre-kernel).
// ---------------------------------------------------------------------------

#define BTOT   524288
#define MTILE  128
#define NTILES (BTOT / MTILE)   // 4096
#define NTHREADS 512

#define XP_LD 112               // bytes/row (96 used: 0-63 h, 64-65 keep, pad)
#define XP_BYTES (128 * XP_LD)  // 14336
#define W1_LD 112               // bytes/row (96 used)
#define W2_LD 144               // bytes/row (128 used)
#define W3_LD 16                // bf16 elems/row

// smem byte offsets
#define OFF_W1 0                // 256*112 = 28672
#define OFF_W2 28672            // 2*128*144 = 36864 -> 65536
#define OFF_W3 65536            // 128*16*2 = 4096 -> 69632
#define OFF_XP 69632            // 2*14336 = 28672 -> 98304
#define OFF_XA 98304            // 2*2048 -> 102400
#define OFF_B1 102400           // 1024
#define OFF_B2 103424           // 1024
#define OFF_B3 104448           // 32
#define OFF_ST 104480           // 2*2048
#define SMEM_BYTES 108576

__device__ float g_x[BTOT * 4];
__device__ float g_ld[BTOT];
__device__ unsigned char g_hf8[(long)BTOT * 64];

__device__ __forceinline__ uint32_t smem_u32(const void* p) {
    return static_cast<uint32_t>(__cvta_generic_to_shared(p));
}
__device__ __forceinline__ void cp_async16(uint32_t dst, const void* src) {
    asm volatile("cp.async.cg.shared.global [%0], [%1], 16;"
                 :: "r"(dst), "l"(src) : "memory");
}
#define CP_COMMIT() asm volatile("cp.async.commit_group;" ::: "memory")
#define CP_WAIT0()  asm volatile("cp.async.wait_group 0;" ::: "memory")

__device__ __forceinline__ void ldsm_x4(uint32_t a, uint32_t& r0, uint32_t& r1,
                                        uint32_t& r2, uint32_t& r3) {
    asm volatile("ldmatrix.sync.aligned.m8n8.x4.shared.b16 {%0,%1,%2,%3},[%4];"
                 : "=r"(r0), "=r"(r1), "=r"(r2), "=r"(r3) : "r"(a));
}
__device__ __forceinline__ void ldsm_x2(uint32_t a, uint32_t& r0, uint32_t& r1) {
    asm volatile("ldmatrix.sync.aligned.m8n8.x2.shared.b16 {%0,%1},[%2];"
                 : "=r"(r0), "=r"(r1) : "r"(a));
}
__device__ __forceinline__ void ldsm_x2t(uint32_t a, uint32_t& r0, uint32_t& r1) {
    asm volatile("ldmatrix.sync.aligned.m8n8.x2.trans.shared.b16 {%0,%1},[%2];"
                 : "=r"(r0), "=r"(r1) : "r"(a));
}
__device__ __forceinline__ void mma_bf16(float* c, const uint32_t* a,
                                         uint32_t b0, uint32_t b1) {
    asm volatile(
        "mma.sync.aligned.m16n8k16.row.col.f32.bf16.bf16.f32 "
        "{%0,%1,%2,%3},{%4,%5,%6,%7},{%8,%9},{%0,%1,%2,%3};"
        : "+f"(c[0]), "+f"(c[1]), "+f"(c[2]), "+f"(c[3])
        : "r"(a[0]), "r"(a[1]), "r"(a[2]), "r"(a[3]), "r"(b0), "r"(b1));
}
__device__ __forceinline__ void mma_fp8(float* c, const uint32_t* a,
                                        uint32_t b0, uint32_t b1) {
    asm volatile(
        "mma.sync.aligned.m16n8k32.row.col.f32.e4m3.e4m3.f32 "
        "{%0,%1,%2,%3},{%4,%5,%6,%7},{%8,%9},{%0,%1,%2,%3};"
        : "+f"(c[0]), "+f"(c[1]), "+f"(c[2]), "+f"(c[3])
        : "r"(a[0]), "r"(a[1]), "r"(a[2]), "r"(a[3]), "r"(b0), "r"(b1));
}
// e4m3 pair: byte1 = cvt(hi), byte0 = cvt(lo)
__device__ __forceinline__ unsigned short f2e4m3x2(float hi, float lo) {
    unsigned short r;
    asm("cvt.rn.satfinite.e4m3x2.f32 %0, %1, %2;" : "=h"(r) : "f"(hi), "f"(lo));
    return r;
}
__device__ __forceinline__ uint32_t merge16(unsigned short lo, unsigned short hi) {
    uint32_t r;
    asm("mov.b32 %0, {%1, %2};" : "=r"(r) : "h"(lo), "h"(hi));
    return r;
}
__device__ __forceinline__ uint32_t pack_bf2(float lo, float hi) {
    __nv_bfloat162 v = __floats2bfloat162_rn(lo, hi);
    return *reinterpret_cast<uint32_t*>(&v);
}
// f32 tanh-approx GELU, output scaled x16 (for fp8 hid1 storage)
__device__ __forceinline__ float gelu16(float x) {
    float x2 = x * x;
    float w  = fmaf(0.035677408136f, x2, 0.7978845608028654f);
    float u  = x * w;
    float th;
    asm("tanh.approx.f32 %0, %1;" : "=f"(th) : "f"(u));
    float hx = 8.0f * x;   // 16 * 0.5
    return fmaf(hx, th, hx);
}
// packed bf16x2 tanh-approx GELU (hid2 path, unchanged)
__device__ __forceinline__ uint32_t gelu2(uint32_t xin) {
    __nv_bfloat162 x = *reinterpret_cast<__nv_bfloat162*>(&xin);
    const __nv_bfloat162 c1 = __floats2bfloat162_rn(0.035677408136f, 0.035677408136f);
    const __nv_bfloat162 c0 = __floats2bfloat162_rn(0.7978845608028654f, 0.7978845608028654f);
    const __nv_bfloat162 hf = __floats2bfloat162_rn(0.5f, 0.5f);
    __nv_bfloat162 x2 = __hmul2(x, x);
    __nv_bfloat162 w  = __hfma2(x2, c1, c0);
    __nv_bfloat162 u  = __hmul2(x, w);
    uint32_t th;
    asm("tanh.approx.bf16x2 %0, %1;"
        : "=r"(th) : "r"(*reinterpret_cast<uint32_t*>(&u)));
    __nv_bfloat162 hx = __hmul2(x, hf);
    __nv_bfloat162 r  = __hfma2(hx, *reinterpret_cast<__nv_bfloat162*>(&th), hx);
    return *reinterpret_cast<uint32_t*>(&r);
}

// ---- pre-pass: h fp32 -> e4m3 (16 values per thread) ----
__global__ void __launch_bounds__(256)
cvt_h_kernel(const float* __restrict__ h) {
    long i = ((long)blockIdx.x * 256 + threadIdx.x) * 16;
    const float4* src = reinterpret_cast<const float4*>(h + i);
    float4 a = src[0], b = src[1], c = src[2], d = src[3];
    uint4 o;
    o.x = merge16(f2e4m3x2(a.y, a.x), f2e4m3x2(a.w, a.z));
    o.y = merge16(f2e4m3x2(b.y, b.x), f2e4m3x2(b.w, b.z));
    o.z = merge16(f2e4m3x2(c.y, c.x), f2e4m3x2(c.w, c.z));
    o.w = merge16(f2e4m3x2(d.y, d.x), f2e4m3x2(d.w, d.z));
    *reinterpret_cast<uint4*>(g_hf8 + i) = o;
}

template <int LYR>
__global__ void __launch_bounds__(NTHREADS, 1)
nvp_layer(const float* __restrict__ theta, const float* __restrict__ h,
          const float* __restrict__ w1s, const float* __restrict__ b1s,
          const float* __restrict__ w2s, const float* __restrict__ b2s,
          const float* __restrict__ w3s, const float* __restrict__ b3s,
          const float* __restrict__ w1t, const float* __restrict__ b1t,
          const float* __restrict__ w2t, const float* __restrict__ b2t,
          const float* __restrict__ w3t, const float* __restrict__ b3t,
          float* __restrict__ out)
{
    constexpr bool FIRST = (LYR == 0);
    constexpr bool LAST  = (LYR == 3);
    // KEEP = ((0,1),(1,2),(2,3),(0,3)); TRANS = ((2,3),(0,3),(0,1),(1,2))
    constexpr int K0 = (LYR == 0) ? 0 : (LYR == 1) ? 1 : (LYR == 2) ? 2 : 0;
    constexpr int K1 = (LYR == 0) ? 1 : (LYR == 1) ? 2 : (LYR == 2) ? 3 : 3;
    constexpr int T0 = (LYR == 0) ? 2 : (LYR == 1) ? 0 : (LYR == 2) ? 0 : 1;
    constexpr int T1 = (LYR == 0) ? 3 : (LYR == 1) ? 3 : (LYR == 2) ? 1 : 2;

    extern __shared__ char smem[];
    const uint32_t smem_base = smem_u32(smem);
    __nv_bfloat16* sW3 = reinterpret_cast<__nv_bfloat16*>(smem + OFF_W3);
    float* sB1 = reinterpret_cast<float*>(smem + OFF_B1);
    float* sB2 = reinterpret_cast<float*>(smem + OFF_B2);
    float* sB3 = reinterpret_cast<float*>(smem + OFF_B3);

    const int tid = threadIdx.x;

    // ---- one-time weights -> smem ----
    // W1 fp8 [n=256][k]: k 0..63 = 32*w1[k+2][n], 64..65 = 32*w1[0..1][n], pad 0
    for (int idx = tid; idx < 256 * 56; idx += NTHREADS) {
        int n = idx / 56, kp = idx - n * 56;
        const float* w1 = (n < 128) ? w1s : w1t;
        int nn = n & 127;
        int k0 = kp * 2;
        float v0 = 0.f, v1 = 0.f;
        {
            int k = k0;
            if (k < 64) v0 = w1[(k + 2) * 128 + nn];
            else if (k == 64) v0 = w1[nn];
            else if (k == 65) v0 = w1[128 + nn];
            k = k0 + 1;
            if (k < 64) v1 = w1[(k + 2) * 128 + nn];
            else if (k == 64) v1 = w1[nn];
            else if (k == 65) v1 = w1[128 + nn];
        }
        *reinterpret_cast<unsigned short*>(smem + OFF_W1 + n * W1_LD + k0) =
            f2e4m3x2(32.f * v1, 32.f * v0);
    }
    // W2 fp8 [net][n=128][kk]: value = 32*w2[pi(kk)][n]
    for (int idx = tid; idx < 2 * 128 * 72; idx += NTHREADS) {
        int net = idx / 9216;
        int r = idx - net * 9216;
        int n = r / 72, kp = r - n * 72;
        const float* w2 = net ? w2t : w2s;
        int k0 = kp * 2;
        float v0 = 0.f, v1 = 0.f;
        #pragma unroll
        for (int d = 0; d < 2; d++) {
            int k = k0 + d;
            if (k < 128) {
                int ks = k >> 5, rem = k & 31, hh = rem >> 4;
                int r2 = rem & 15, q = r2 >> 2, b = r2 & 3;
                int col = ((ks << 2) + (hh << 1) + (b >> 1)) * 8 + (q << 1) + (b & 1);
                float v = 32.f * w2[col * 128 + n];
                if (d == 0) v0 = v; else v1 = v;
            }
        }
        *reinterpret_cast<unsigned short*>(
            smem + OFF_W2 + net * 18432 + n * W2_LD + k0) = f2e4m3x2(v1, v0);
    }
    // W3 bf16 [k=128][16]: cols 0-1 = w3s, 8-9 = w3t
    for (int idx = tid; idx < 128 * W3_LD; idx += NTHREADS) {
        int k = idx >> 4, c = idx & 15;
        float v = 0.0f;
        if (c < 2) v = w3s[k * 2 + c];
        else if (c >= 8 && c < 10) v = w3t[k * 2 + c - 8];
        sW3[idx] = __float2bfloat16(v);
    }
    for (int c = tid; c < 256; c += NTHREADS) {
        sB1[c] = (c < 128) ? b1s[c] : b1t[c - 128];
        sB2[c] = (c < 128) ? b2s[c] : b2t[c - 128];
    }
    if (tid < 4) sB3[tid] = (tid < 2) ? b3s[tid] : b3t[tid - 2];
    // zero xp pad bytes [66,112) in BOTH buffers
    for (int idx = tid; idx < 256 * 46; idx += NTHREADS) {
        int rr = idx / 46, c = 66 + (idx - rr * 46);
        smem[OFF_XP + rr * XP_LD + c] = 0;
    }

    const int warp = tid >> 5;
    const int lane = tid & 31;
    const int net  = warp >> 3;
    const int R0   = (warp & 7) * 16;
    const int lg   = lane >> 3;
    const int lr   = lane & 7;
    const int q2   = (lane & 3) * 2;

    // lane-level B base addresses (byte units)
    const uint32_t b1base  = smem_base + OFF_W1 + (net * 128 + lr) * W1_LD
                           + ((lane >> 3) & 3) * 16;   // note: uses lane&7 rows
    const uint32_t b1base2 = smem_base + OFF_W1 + (net * 128 + lr) * W1_LD
                           + 64 + ((lane >> 3) & 1) * 16;
    const uint32_t b2base  = smem_base + OFF_W2 + net * 18432 + lr * W2_LD
                           + ((lane >> 3) & 3) * 16;

    // ---- prologue: prefetch tile0 into buf 0 ----
    const int tile0 = blockIdx.x;
    {
        const unsigned char* hsrc = g_hf8 + (long)tile0 * MTILE * 64;
        uint32_t xpn = smem_base + OFF_XP;
        for (int c = tid; c < 512; c += NTHREADS) {
            int r = c >> 2, q = c & 3;
            cp_async16(xpn + r * XP_LD + q * 16, hsrc + r * 64 + q * 16);
        }
        if (tid < 128) {
            const float* xsrc = FIRST ? (theta + (long)(tile0 * MTILE + tid) * 4)
                                      : (g_x + (long)(tile0 * MTILE + tid) * 4);
            cp_async16(smem_base + OFF_XA + tid * 16, xsrc);
        }
        CP_COMMIT();
        CP_WAIT0();
        if (tid < 128) {
            float4 nx = *reinterpret_cast<float4*>(smem + OFF_XA + tid * 16);
            float c4[4] = {nx.x, nx.y, nx.z, nx.w};
            *reinterpret_cast<unsigned short*>(
                smem + OFF_XP + tid * XP_LD + 64) = f2e4m3x2(c4[K1], c4[K0]);
        }
    }
    __syncthreads();

    const float inv32 = 0.03125f, inv512 = 0.001953125f;
    int buf = 0;
    for (int tile = tile0; tile < NTILES; tile += gridDim.x) {
        const int base = tile * MTILE;
        const int nt = tile + gridDim.x;
        const bool has_next = (nt < NTILES);

        if (has_next) {
            const unsigned char* hsrc = g_hf8 + (long)nt * MTILE * 64;
            uint32_t xpn = smem_base + OFF_XP + (buf ^ 1) * XP_BYTES;
            for (int c = tid; c < 512; c += NTHREADS) {
                int r = c >> 2, q = c & 3;
                cp_async16(xpn + r * XP_LD + q * 16, hsrc + r * 64 + q * 16);
            }
            if (tid < 128) {
                const float* xsrc = FIRST ? (theta + (long)(nt * MTILE + tid) * 4)
                                          : (g_x + (long)(nt * MTILE + tid) * 4);
                cp_async16(smem_base + OFF_XA + (buf ^ 1) * 2048 + tid * 16, xsrc);
            }
            CP_COMMIT();
        }

        float* sST = reinterpret_cast<float*>(smem + OFF_ST + buf * 2048);

        // ---- A frags from xp (fp8, k=96 -> 3 k32-steps) ----
        uint32_t axp[3][4];
        {
            uint32_t pa = smem_base + OFF_XP + buf * XP_BYTES
                        + (R0 + lr + (lg & 1) * 8) * XP_LD + (lg >> 1) * 16;
            ldsm_x4(pa,      axp[0][0], axp[0][1], axp[0][2], axp[0][3]);
            ldsm_x4(pa + 32, axp[1][0], axp[1][1], axp[1][2], axp[1][3]);
            ldsm_x4(pa + 64, axp[2][0], axp[2][1], axp[2][2], axp[2][3]);
        }

        // ---- GEMM1 (fp8) + epi1 -> A2 (fp8 hid1, permuted) ----
        uint32_t A2[4][4];
        unsigned short p01 = 0, p23 = 0;
        #pragma unroll
        for (int g = 0; g < 16; g++) {
            uint32_t b0, b1, b2, b3, c0, c1;
            ldsm_x4(b1base + g * (8 * W1_LD), b0, b1, b2, b3);
            ldsm_x2(b1base2 + g * (8 * W1_LD), c0, c1);
            float acc[4] = {0.f, 0.f, 0.f, 0.f};
            mma_fp8(acc, axp[0], b0, b1);
            mma_fp8(acc, axp[1], b2, b3);
            mma_fp8(acc, axp[2], c0, c1);
            float2 bb = *reinterpret_cast<const float2*>(&sB1[net * 128 + g * 8 + q2]);
            float v0 = gelu16(fmaf(acc[0], inv32, bb.x));
            float v1 = gelu16(fmaf(acc[1], inv32, bb.y));
            float v2 = gelu16(fmaf(acc[2], inv32, bb.x));
            float v3 = gelu16(fmaf(acc[3], inv32, bb.y));
            unsigned short t01 = f2e4m3x2(v1, v0);
            unsigned short t23 = f2e4m3x2(v3, v2);
            if (g & 1) {
                int ks = g >> 2, hi2 = (g >> 1) & 1;
                A2[ks][hi2 * 2 + 0] = merge16(p01, t01);
                A2[ks][hi2 * 2 + 1] = merge16(p23, t23);
            } else { p01 = t01; p23 = t23; }
        }

        // ---- GEMM2 (fp8) + epi2 (bf16) + GEMM3 (bf16) ----
        float acc3[4] = {0.f, 0.f, 0.f, 0.f};
        #pragma unroll
        for (int cc = 0; cc < 2; cc++) {
            uint32_t af[4][4];
            #pragma unroll
            for (int gg = 0; gg < 8; gg++) {
                int g = cc * 8 + gg;
                uint32_t r0, r1, r2, r3, r4, r5, r6, r7;
                ldsm_x4(b2base + g * (8 * W2_LD),      r0, r1, r2, r3);
                ldsm_x4(b2base + g * (8 * W2_LD) + 64, r4, r5, r6, r7);
                float acc[4] = {0.f, 0.f, 0.f, 0.f};
                mma_fp8(acc, A2[0], r0, r1);
                mma_fp8(acc, A2[1], r2, r3);
                mma_fp8(acc, A2[2], r4, r5);
                mma_fp8(acc, A2[3], r6, r7);
                float2 bb = *reinterpret_cast<const float2*>(&sB2[net * 128 + g * 8 + q2]);
                uint32_t u0 = gelu2(pack_bf2(fmaf(acc[0], inv512, bb.x),
                                             fmaf(acc[1], inv512, bb.y)));
                uint32_t u1 = gelu2(pack_bf2(fmaf(acc[2], inv512, bb.x),
                                             fmaf(acc[3], inv512, bb.y)));
                af[gg >> 1][(gg & 1) * 2 + 0] = u0;
                af[gg >> 1][(gg & 1) * 2 + 1] = u1;
            }
            #pragma unroll
            for (int kf = 0; kf < 4; kf++) {
                int k0 = cc * 64 + kf * 16;
                uint32_t addr = smem_u32(&sW3[(k0 + (lane & 15)) * W3_LD + net * 8]);
                uint32_t w0, w1r;
                ldsm_x2t(addr, w0, w1r);
                mma_bf16(acc3, af[kf], w0, w1r);
            }
        }

        // ---- stage s/t into sST[buf] ----
        if ((lane & 3) == 0) {
            int r1 = lane >> 2;
            #pragma unroll
            for (int half = 0; half < 2; half++) {
                int row = R0 + r1 + half * 8;
                sST[(net * 128 + row) * 2 + 0] = acc3[half * 2 + 0];
                sST[(net * 128 + row) * 2 + 1] = acc3[half * 2 + 1];
            }
        }

        // current-tile x into regs (sXA[buf] final since last iteration)
        float4 xv = make_float4(0.f, 0.f, 0.f, 0.f);
        if (tid < 128)
            xv = *reinterpret_cast<float4*>(smem + OFF_XA + buf * 2048 + tid * 16);

        // finish next-tile prefetch: wait + x-keep fp8 into xp[buf^1]
        if (has_next) {
            CP_WAIT0();
            if (tid < 128) {
                float4 nx = *reinterpret_cast<float4*>(
                    smem + OFF_XA + (buf ^ 1) * 2048 + tid * 16);
                float c4[4] = {nx.x, nx.y, nx.z, nx.w};
                *reinterpret_cast<unsigned short*>(
                    smem + OFF_XP + (buf ^ 1) * XP_BYTES + tid * XP_LD + 64) =
                    f2e4m3x2(c4[K1], c4[K0]);
            }
        }
        __syncthreads();

        // ---- epilogue: one thread per row ----
        if (tid < 128) {
            int row = tid;
            int b = base + row;
            float s0 = sST[row * 2 + 0] + sB3[0];
            float s1 = sST[row * 2 + 1] + sB3[1];
            float t0 = sST[(128 + row) * 2 + 0] + sB3[2];
            float t1 = sST[(128 + row) * 2 + 1] + sB3[3];
            float xc[4] = {xv.x, xv.y, xv.z, xv.w};
            float nx0 = xc[T0] * __expf(s0) + t0;
            float nx1 = xc[T1] * __expf(s1) + t1;
            float ld = s0 + s1;
            if (!FIRST) ld += g_ld[b];
            xc[T0] = nx0;
            xc[T1] = nx1;
            if (!LAST) {
                reinterpret_cast<float4*>(g_x)[b] =
                    make_float4(xc[0], xc[1], xc[2], xc[3]);
                g_ld[b] = ld;
            } else {
                float ss = xc[0] * xc[0] + xc[1] * xc[1] +
                           xc[2] * xc[2] + xc[3] * xc[3];
                out[b] = -0.5f * ss - 3.6757541328186907f + ld;
            }
        }
        buf ^= 1;
    }
}

extern "C" void kernel_launch(void* const* d_in, const int* in_sizes, int n_in,
                              void* d_out, int out_size)
{
    const float* theta = (const float*)d_in[0];
    const float* h     = (const float*)d_in[1];
    const float* sW1   = (const float*)d_in[2];
    const float* sb1   = (const float*)d_in[3];
    const float* sW2   = (const float*)d_in[4];
    const float* sb2   = (const float*)d_in[5];
    const float* sW3   = (const float*)d_in[6];
    const float* sb3   = (const float*)d_in[7];
    const float* tW1   = (const float*)d_in[8];
    const float* tb1   = (const float*)d_in[9];
    const float* tW2   = (const float*)d_in[10];
    const float* tb2   = (const float*)d_in[11];
    const float* tW3   = (const float*)d_in[12];
    const float* tb3   = (const float*)d_in[13];
    float* out = (float*)d_out;

    int nsm = 148;
    cudaDeviceGetAttribute(&nsm, cudaDevAttrMultiProcessorCount, 0);

    cudaFuncSetAttribute(nvp_layer<0>, cudaFuncAttributeMaxDynamicSharedMemorySize, SMEM_BYTES);
    cudaFuncSetAttribute(nvp_layer<1>, cudaFuncAttributeMaxDynamicSharedMemorySize, SMEM_BYTES);
    cudaFuncSetAttribute(nvp_layer<2>, cudaFuncAttributeMaxDynamicSharedMemorySize, SMEM_BYTES);
    cudaFuncSetAttribute(nvp_layer<3>, cudaFuncAttributeMaxDynamicSharedMemorySize, SMEM_BYTES);

    // pre-pass: h -> e4m3 (BTOT*64 values, 16 per thread)
    cvt_h_kernel<<<(BTOT * 64) / (16 * 256), 256>>>(h);

    dim3 grid(nsm), blk(NTHREADS);
    #define ARGS(L) theta, h,                                        \
        sW1 + (L) * 66 * 128, sb1 + (L) * 128,                       \
        sW2 + (L) * 128 * 128, sb2 + (L) * 128,                      \
        sW3 + (L) * 128 * 2, sb3 + (L) * 2,                          \
        tW1 + (L) * 66 * 128, tb1 + (L) * 128,                       \
        tW2 + (L) * 128 * 128, tb2 + (L) * 128,                      \
        tW3 + (L) * 128 * 2, tb3 + (L) * 2, out

    nvp_layer<0><<<grid, blk, SMEM_BYTES>>>(ARGS(0));
    nvp_layer<1><<<grid, blk, SMEM_BYTES>>>(ARGS(1));
    nvp_layer<2><<<grid, blk, SMEM_BYTES>>>(ARGS(2));
    nvp_layer<3><<<grid, blk, SMEM_BYTES>>>(ARGS(3));
    #undef ARGS
}

// round 10
// speedup vs baseline: 1.1205x; 1.1205x over previous
#include <cuda_runtime.h>
#include <cuda_bf16.h>
#include <cstdint>

// ---------------------------------------------------------------------------
// ConditionalRealNVP log_prob — R9: R7 structure (bf16 WMMA, cp.async double
// buffer, packed gelu, bias-fold) with DOUBLE-M warps:
//   256 threads / 8 warps; each warp owns 32 rows x 128 cols (its net),
//   two m16 tiles sharing every B fragment -> B-LDSM bytes and address alu
//   halve, HMMA:LDSM ILP doubles. Regfile: 255 regs/thread available.
// ---------------------------------------------------------------------------

#define BTOT   524288
#define MTILE  128
#define NTILES (BTOT / MTILE)   // 4096
#define XP_LD  88
#define W_LD   264
#define W3_LD  16
#define NTHREADS 256
#define XP_BYTES (128 * XP_LD * 2)   // 22528

// smem byte offsets
#define OFF_W1  0                  // 80*264*2  = 42240
#define OFF_W2  42240              // 128*264*2 = 67584
#define OFF_W3  109824             // 128*16*2  = 4096
#define OFF_XP  113920             // 2 x 22528 = 45056
#define OFF_XA  158976             // 2 x 2048  = 4096
#define OFF_B1  163072             // 1024
#define OFF_B2  164096             // 1024
#define OFF_B3  165120             // 32
#define OFF_ST  165152             // 2 x 2048  = 4096
#define SMEM_BYTES 169248

__device__ float g_x[BTOT * 4];
__device__ float g_ld[BTOT];
__device__ __nv_bfloat16 g_hbf[(long)BTOT * 64];

__device__ __forceinline__ uint32_t smem_u32(const void* p) {
    return static_cast<uint32_t>(__cvta_generic_to_shared(p));
}
__device__ __forceinline__ void cp_async16(uint32_t dst, const void* src) {
    asm volatile("cp.async.cg.shared.global [%0], [%1], 16;"
                 :: "r"(dst), "l"(src) : "memory");
}
#define CP_COMMIT() asm volatile("cp.async.commit_group;" ::: "memory")
#define CP_WAIT0()  asm volatile("cp.async.wait_group 0;" ::: "memory")

__device__ __forceinline__ void ldsm_x4(uint32_t a, uint32_t& r0, uint32_t& r1,
                                        uint32_t& r2, uint32_t& r3) {
    asm volatile("ldmatrix.sync.aligned.m8n8.x4.shared.b16 {%0,%1,%2,%3},[%4];"
                 : "=r"(r0), "=r"(r1), "=r"(r2), "=r"(r3) : "r"(a));
}
__device__ __forceinline__ void ldsm_x4t(uint32_t a, uint32_t& r0, uint32_t& r1,
                                         uint32_t& r2, uint32_t& r3) {
    asm volatile("ldmatrix.sync.aligned.m8n8.x4.trans.shared.b16 {%0,%1,%2,%3},[%4];"
                 : "=r"(r0), "=r"(r1), "=r"(r2), "=r"(r3) : "r"(a));
}
__device__ __forceinline__ void ldsm_x2t(uint32_t a, uint32_t& r0, uint32_t& r1) {
    asm volatile("ldmatrix.sync.aligned.m8n8.x2.trans.shared.b16 {%0,%1},[%2];"
                 : "=r"(r0), "=r"(r1) : "r"(a));
}
__device__ __forceinline__ void mma_bf16(float* c, const uint32_t* a,
                                         uint32_t b0, uint32_t b1) {
    asm volatile(
        "mma.sync.aligned.m16n8k16.row.col.f32.bf16.bf16.f32 "
        "{%0,%1,%2,%3},{%4,%5,%6,%7},{%8,%9},{%0,%1,%2,%3};"
        : "+f"(c[0]), "+f"(c[1]), "+f"(c[2]), "+f"(c[3])
        : "r"(a[0]), "r"(a[1]), "r"(a[2]), "r"(a[3]), "r"(b0), "r"(b1));
}
__device__ __forceinline__ uint32_t pack_bf2(float lo, float hi) {
    __nv_bfloat162 v = __floats2bfloat162_rn(lo, hi);
    return *reinterpret_cast<uint32_t*>(&v);
}
// packed bf16x2 tanh-approx GELU
__device__ __forceinline__ uint32_t gelu2(uint32_t xin) {
    __nv_bfloat162 x = *reinterpret_cast<__nv_bfloat162*>(&xin);
    const __nv_bfloat162 c1 = __floats2bfloat162_rn(0.035677408136f, 0.035677408136f);
    const __nv_bfloat162 c0 = __floats2bfloat162_rn(0.7978845608028654f, 0.7978845608028654f);
    const __nv_bfloat162 hf = __floats2bfloat162_rn(0.5f, 0.5f);
    __nv_bfloat162 x2 = __hmul2(x, x);
    __nv_bfloat162 w  = __hfma2(x2, c1, c0);
    __nv_bfloat162 u  = __hmul2(x, w);
    uint32_t th;
    asm("tanh.approx.bf16x2 %0, %1;"
        : "=r"(th) : "r"(*reinterpret_cast<uint32_t*>(&u)));
    __nv_bfloat162 hx = __hmul2(x, hf);
    __nv_bfloat162 r  = __hfma2(hx, *reinterpret_cast<__nv_bfloat162*>(&th), hx);
    return *reinterpret_cast<uint32_t*>(&r);
}

__device__ __forceinline__ void ldB4(const __nv_bfloat16* p, uint32_t bf[4][4]) {
    #pragma unroll
    for (int q = 0; q < 4; q++)
        ldsm_x4t(smem_u32(p + q * 16), bf[q][0], bf[q][1], bf[q][2], bf[q][3]);
}
__device__ __forceinline__ void mma8(float acc[8][4], const uint32_t* A,
                                     uint32_t bf[4][4]) {
    #pragma unroll
    for (int q = 0; q < 4; q++) {
        mma_bf16(acc[2 * q],     A, bf[q][0], bf[q][1]);
        mma_bf16(acc[2 * q + 1], A, bf[q][2], bf[q][3]);
    }
}
// dual-M: two independent accumulator sets share one B fragment group
__device__ __forceinline__ void mma8x2(float a0[8][4], float a1[8][4],
                                       const uint32_t* A0, const uint32_t* A1,
                                       uint32_t bf[4][4]) {
    #pragma unroll
    for (int q = 0; q < 4; q++) {
        mma_bf16(a0[2 * q],     A0, bf[q][0], bf[q][1]);
        mma_bf16(a1[2 * q],     A1, bf[q][0], bf[q][1]);
        mma_bf16(a0[2 * q + 1], A0, bf[q][2], bf[q][3]);
        mma_bf16(a1[2 * q + 1], A1, bf[q][2], bf[q][3]);
    }
}

// ---- pre-pass: h fp32 -> bf16 (run once per graph replay) ----
__global__ void __launch_bounds__(256)
cvt_h_kernel(const float* __restrict__ h) {
    long i = ((long)blockIdx.x * 256 + threadIdx.x) * 8;
    float4 a = *reinterpret_cast<const float4*>(h + i);
    float4 b = *reinterpret_cast<const float4*>(h + i + 4);
    uint4 o;
    o.x = pack_bf2(a.x, a.y); o.y = pack_bf2(a.z, a.w);
    o.z = pack_bf2(b.x, b.y); o.w = pack_bf2(b.z, b.w);
    *reinterpret_cast<uint4*>(g_hbf + i) = o;
}

template <int LYR>
__global__ void __launch_bounds__(NTHREADS, 1)
nvp_layer(const float* __restrict__ theta, const float* __restrict__ h,
          const float* __restrict__ w1s, const float* __restrict__ b1s,
          const float* __restrict__ w2s, const float* __restrict__ b2s,
          const float* __restrict__ w3s, const float* __restrict__ b3s,
          const float* __restrict__ w1t, const float* __restrict__ b1t,
          const float* __restrict__ w2t, const float* __restrict__ b2t,
          const float* __restrict__ w3t, const float* __restrict__ b3t,
          float* __restrict__ out)
{
    constexpr bool FIRST = (LYR == 0);
    constexpr bool LAST  = (LYR == 3);
    // KEEP = ((0,1),(1,2),(2,3),(0,3)); TRANS = ((2,3),(0,3),(0,1),(1,2))
    constexpr int K0 = (LYR == 0) ? 0 : (LYR == 1) ? 1 : (LYR == 2) ? 2 : 0;
    constexpr int K1 = (LYR == 0) ? 1 : (LYR == 1) ? 2 : (LYR == 2) ? 3 : 3;
    constexpr int T0 = (LYR == 0) ? 2 : (LYR == 1) ? 0 : (LYR == 2) ? 0 : 1;
    constexpr int T1 = (LYR == 0) ? 3 : (LYR == 1) ? 3 : (LYR == 2) ? 1 : 2;

    extern __shared__ char smem[];
    const uint32_t smem_base = smem_u32(smem);
    __nv_bfloat16* sW1 = reinterpret_cast<__nv_bfloat16*>(smem + OFF_W1);
    __nv_bfloat16* sW2 = reinterpret_cast<__nv_bfloat16*>(smem + OFF_W2);
    __nv_bfloat16* sW3 = reinterpret_cast<__nv_bfloat16*>(smem + OFF_W3);
    float* sB1 = reinterpret_cast<float*>(smem + OFF_B1);
    float* sB2 = reinterpret_cast<float*>(smem + OFF_B2);
    float* sB3 = reinterpret_cast<float*>(smem + OFF_B3);

    const int tid = threadIdx.x;

    // ---- one-time weights -> smem ----
    // W1 rows: 0..63 = w1[k+2] (h part), 64..65 = w1[0..1] (x-keep), 66..79 = 0
    for (int idx = tid; idx < 80 * W_LD; idx += NTHREADS) {
        int k = idx / W_LD, c = idx - k * W_LD;
        float v = 0.0f;
        if (c < 256) {
            const float* w1 = (c < 128) ? w1s : w1t;
            int cc = c & 127;
            if (k < 64)      v = w1[(k + 2) * 128 + cc];
            else if (k < 66) v = w1[(k - 64) * 128 + cc];
        }
        sW1[idx] = __float2bfloat16(v);
    }
    for (int idx = tid; idx < 128 * W_LD; idx += NTHREADS) {
        int k = idx / W_LD, c = idx - k * W_LD;
        float v = 0.0f;
        if (c < 256) v = (c < 128) ? w2s[k * 128 + c] : w2t[k * 128 + c - 128];
        sW2[idx] = __float2bfloat16(v);
    }
    for (int idx = tid; idx < 128 * W3_LD; idx += NTHREADS) {
        int k = idx >> 4, c = idx & 15;
        float v = 0.0f;
        if (c < 2) v = w3s[k * 2 + c];
        else if (c >= 8 && c < 10) v = w3t[k * 2 + c - 8];
        sW3[idx] = __float2bfloat16(v);
    }
    for (int c = tid; c < 256; c += NTHREADS) {
        sB1[c] = (c < 128) ? b1s[c] : b1t[c - 128];
        sB2[c] = (c < 128) ? b2s[c] : b2t[c - 128];
    }
    if (tid < 4) sB3[tid] = (tid < 2) ? b3s[tid] : b3t[tid - 2];
    // zero xp pad cols [66,88) in BOTH buffers (never rewritten)
    for (int idx = tid; idx < 2 * 128 * 22; idx += NTHREADS) {
        int bufr = idx / 22, c = 66 + (idx - bufr * 22);
        int bb = bufr >> 7, r = bufr & 127;
        *reinterpret_cast<__nv_bfloat16*>(
            smem + OFF_XP + bb * XP_BYTES + (r * XP_LD + c) * 2) =
            __float2bfloat16(0.0f);
    }

    const int warp = tid >> 5;        // 0..7
    const int lane = tid & 31;
    const int net  = warp >> 2;       // 0 = s-net, 1 = t-net
    const int R0   = (warp & 3) * 32; // 32-row block (two m16 tiles)
    const int lg   = lane >> 3;
    const int lr   = lane & 7;

    // ---- prologue: prefetch tile0 into buf 0 ----
    const int tile0 = blockIdx.x;
    {
        const __nv_bfloat16* hsrc = g_hbf + (long)tile0 * MTILE * 64;
        uint32_t xpn = smem_base + OFF_XP;
        #pragma unroll
        for (int c = tid; c < 1024; c += NTHREADS) {
            int r = c >> 3, q = c & 7;
            cp_async16(xpn + r * 176 + q * 16, hsrc + r * 64 + q * 8);
        }
        if (tid < 128) {
            const float* xsrc = FIRST ? (theta + (long)(tile0 * MTILE + tid) * 4)
                                      : (g_x + (long)(tile0 * MTILE + tid) * 4);
            cp_async16(smem_base + OFF_XA + tid * 16, xsrc);
        }
        CP_COMMIT();
        CP_WAIT0();
        if (tid < 128) {
            float4 nx = *reinterpret_cast<float4*>(smem + OFF_XA + tid * 16);
            float c4[4] = {nx.x, nx.y, nx.z, nx.w};
            *reinterpret_cast<__nv_bfloat162*>(smem + OFF_XP + tid * 176 + 128) =
                __floats2bfloat162_rn(c4[K0], c4[K1]);
        }
    }
    __syncthreads();

    int buf = 0;
    for (int tile = tile0; tile < NTILES; tile += gridDim.x) {
        const int base = tile * MTILE;
        const int nt = tile + gridDim.x;
        const bool has_next = (nt < NTILES);

        // ---- prefetch next tile into buf^1 ----
        if (has_next) {
            const __nv_bfloat16* hsrc = g_hbf + (long)nt * MTILE * 64;
            uint32_t xpn = smem_base + OFF_XP + (buf ^ 1) * XP_BYTES;
            #pragma unroll
            for (int c = tid; c < 1024; c += NTHREADS) {
                int r = c >> 3, q = c & 7;
                cp_async16(xpn + r * 176 + q * 16, hsrc + r * 64 + q * 8);
            }
            if (tid < 128) {
                const float* xsrc = FIRST ? (theta + (long)(nt * MTILE + tid) * 4)
                                          : (g_x + (long)(nt * MTILE + tid) * 4);
                cp_async16(smem_base + OFF_XA + (buf ^ 1) * 2048 + tid * 16, xsrc);
            }
            CP_COMMIT();
        }

        __nv_bfloat16* sXP = reinterpret_cast<__nv_bfloat16*>(
            smem + OFF_XP + buf * XP_BYTES);
        float* sST = reinterpret_cast<float*>(smem + OFF_ST + buf * 2048);

        // ---- GEMM1: A frags from xp (K=80) for BOTH m16 tiles ----
        uint32_t axp[2][5][4];
        #pragma unroll
        for (int mt = 0; mt < 2; mt++) {
            int row = R0 + mt * 16 + lr + (lg & 1) * 8;
            const __nv_bfloat16* pbase = &sXP[row * XP_LD + (lg >> 1) * 8];
            #pragma unroll
            for (int ks = 0; ks < 5; ks++)
                ldsm_x4(smem_u32(pbase + ks * 16), axp[mt][ks][0],
                        axp[mt][ks][1], axp[mt][ks][2], axp[mt][ks][3]);
        }
        uint32_t hfr[2][8][4];
        #pragma unroll
        for (int ch = 0; ch < 2; ch++) {
            float acc0[8][4], acc1[8][4];
            #pragma unroll
            for (int j = 0; j < 8; j++) {
                int c = net * 128 + ch * 64 + j * 8 + (lane & 3) * 2;
                float2 bb = *reinterpret_cast<const float2*>(&sB1[c]);
                acc0[j][0] = bb.x; acc0[j][1] = bb.y;
                acc0[j][2] = bb.x; acc0[j][3] = bb.y;
                acc1[j][0] = bb.x; acc1[j][1] = bb.y;
                acc1[j][2] = bb.x; acc1[j][3] = bb.y;
            }
            const __nv_bfloat16* wb =
                &sW1[(lr + (lg & 1) * 8) * W_LD + net * 128 + ch * 64 + (lg >> 1) * 8];
            uint32_t bfa[4][4], bfb[4][4];
            ldB4(wb, bfa);
            ldB4(wb + 16 * W_LD, bfb);  mma8x2(acc0, acc1, axp[0][0], axp[1][0], bfa);
            ldB4(wb + 32 * W_LD, bfa);  mma8x2(acc0, acc1, axp[0][1], axp[1][1], bfb);
            ldB4(wb + 48 * W_LD, bfb);  mma8x2(acc0, acc1, axp[0][2], axp[1][2], bfa);
            ldB4(wb + 64 * W_LD, bfa);  mma8x2(acc0, acc1, axp[0][3], axp[1][3], bfb);
                                        mma8x2(acc0, acc1, axp[0][4], axp[1][4], bfa);
            #pragma unroll
            for (int kf = 0; kf < 4; kf++) {
                hfr[0][ch * 4 + kf][0] = gelu2(pack_bf2(acc0[2 * kf][0], acc0[2 * kf][1]));
                hfr[0][ch * 4 + kf][1] = gelu2(pack_bf2(acc0[2 * kf][2], acc0[2 * kf][3]));
                hfr[0][ch * 4 + kf][2] = gelu2(pack_bf2(acc0[2 * kf + 1][0], acc0[2 * kf + 1][1]));
                hfr[0][ch * 4 + kf][3] = gelu2(pack_bf2(acc0[2 * kf + 1][2], acc0[2 * kf + 1][3]));
                hfr[1][ch * 4 + kf][0] = gelu2(pack_bf2(acc1[2 * kf][0], acc1[2 * kf][1]));
                hfr[1][ch * 4 + kf][1] = gelu2(pack_bf2(acc1[2 * kf][2], acc1[2 * kf][3]));
                hfr[1][ch * 4 + kf][2] = gelu2(pack_bf2(acc1[2 * kf + 1][0], acc1[2 * kf + 1][1]));
                hfr[1][ch * 4 + kf][3] = gelu2(pack_bf2(acc1[2 * kf + 1][2], acc1[2 * kf + 1][3]));
            }
        }

        // ---- GEMM2 (+fused GEMM3), dual-M ----
        float acc3[2][4] = {{0.f, 0.f, 0.f, 0.f}, {0.f, 0.f, 0.f, 0.f}};
        #pragma unroll
        for (int cc = 0; cc < 2; cc++) {
            float acc0[8][4], acc1[8][4];
            #pragma unroll
            for (int j = 0; j < 8; j++) {
                int c = net * 128 + cc * 64 + j * 8 + (lane & 3) * 2;
                float2 bb = *reinterpret_cast<const float2*>(&sB2[c]);
                acc0[j][0] = bb.x; acc0[j][1] = bb.y;
                acc0[j][2] = bb.x; acc0[j][3] = bb.y;
                acc1[j][0] = bb.x; acc1[j][1] = bb.y;
                acc1[j][2] = bb.x; acc1[j][3] = bb.y;
            }
            const __nv_bfloat16* wb =
                &sW2[(lr + (lg & 1) * 8) * W_LD + net * 128 + cc * 64 + (lg >> 1) * 8];
            uint32_t bfa[4][4], bfb[4][4];
            ldB4(wb, bfa);
            ldB4(wb +  16 * W_LD, bfb);  mma8x2(acc0, acc1, hfr[0][0], hfr[1][0], bfa);
            ldB4(wb +  32 * W_LD, bfa);  mma8x2(acc0, acc1, hfr[0][1], hfr[1][1], bfb);
            ldB4(wb +  48 * W_LD, bfb);  mma8x2(acc0, acc1, hfr[0][2], hfr[1][2], bfa);
            ldB4(wb +  64 * W_LD, bfa);  mma8x2(acc0, acc1, hfr[0][3], hfr[1][3], bfb);
            ldB4(wb +  80 * W_LD, bfb);  mma8x2(acc0, acc1, hfr[0][4], hfr[1][4], bfa);
            ldB4(wb +  96 * W_LD, bfa);  mma8x2(acc0, acc1, hfr[0][5], hfr[1][5], bfb);
            ldB4(wb + 112 * W_LD, bfb);  mma8x2(acc0, acc1, hfr[0][6], hfr[1][6], bfa);
                                         mma8x2(acc0, acc1, hfr[0][7], hfr[1][7], bfb);
            uint32_t af0[4][4], af1[4][4];
            #pragma unroll
            for (int kf = 0; kf < 4; kf++) {
                af0[kf][0] = gelu2(pack_bf2(acc0[2 * kf][0], acc0[2 * kf][1]));
                af0[kf][1] = gelu2(pack_bf2(acc0[2 * kf][2], acc0[2 * kf][3]));
                af0[kf][2] = gelu2(pack_bf2(acc0[2 * kf + 1][0], acc0[2 * kf + 1][1]));
                af0[kf][3] = gelu2(pack_bf2(acc0[2 * kf + 1][2], acc0[2 * kf + 1][3]));
                af1[kf][0] = gelu2(pack_bf2(acc1[2 * kf][0], acc1[2 * kf][1]));
                af1[kf][1] = gelu2(pack_bf2(acc1[2 * kf][2], acc1[2 * kf][3]));
                af1[kf][2] = gelu2(pack_bf2(acc1[2 * kf + 1][0], acc1[2 * kf + 1][1]));
                af1[kf][3] = gelu2(pack_bf2(acc1[2 * kf + 1][2], acc1[2 * kf + 1][3]));
            }
            // GEMM3 partial: W3 frags shared by both m-tiles
            #pragma unroll
            for (int kf = 0; kf < 4; kf++) {
                int k0 = cc * 64 + kf * 16;
                uint32_t addr =
                    smem_u32(&sW3[(k0 + (lane & 15)) * W3_LD + net * 8]);
                uint32_t b0, b1;
                ldsm_x2t(addr, b0, b1);
                mma_bf16(acc3[0], af0[kf], b0, b1);
                mma_bf16(acc3[1], af1[kf], b0, b1);
            }
        }

        // ---- stage s/t into sST[buf] ----
        if ((lane & 3) == 0) {
            int r1 = lane >> 2;
            #pragma unroll
            for (int mt = 0; mt < 2; mt++) {
                #pragma unroll
                for (int half = 0; half < 2; half++) {
                    int row = R0 + mt * 16 + r1 + half * 8;
                    sST[(net * 128 + row) * 2 + 0] = acc3[mt][half * 2 + 0];
                    sST[(net * 128 + row) * 2 + 1] = acc3[mt][half * 2 + 1];
                }
            }
        }

        // current-tile x into regs (sXA[buf] final since last iteration)
        float4 xv = make_float4(0.f, 0.f, 0.f, 0.f);
        if (tid < 128)
            xv = *reinterpret_cast<float4*>(smem + OFF_XA + buf * 2048 + tid * 16);

        // finish next-tile prefetch: wait + x-keep conversion into xp[buf^1]
        if (has_next) {
            CP_WAIT0();
            if (tid < 128) {
                float4 nx = *reinterpret_cast<float4*>(
                    smem + OFF_XA + (buf ^ 1) * 2048 + tid * 16);
                float c4[4] = {nx.x, nx.y, nx.z, nx.w};
                *reinterpret_cast<__nv_bfloat162*>(
                    smem + OFF_XP + (buf ^ 1) * XP_BYTES + tid * 176 + 128) =
                    __floats2bfloat162_rn(c4[K0], c4[K1]);
            }
        }
        __syncthreads();

        // ---- epilogue: one thread per row ----
        if (tid < 128) {
            int row = tid;
            int b = base + row;
            float s0 = sST[row * 2 + 0] + sB3[0];
            float s1 = sST[row * 2 + 1] + sB3[1];
            float t0 = sST[(128 + row) * 2 + 0] + sB3[2];
            float t1 = sST[(128 + row) * 2 + 1] + sB3[3];
            float xc[4] = {xv.x, xv.y, xv.z, xv.w};
            float nx0 = xc[T0] * __expf(s0) + t0;
            float nx1 = xc[T1] * __expf(s1) + t1;
            float ld = s0 + s1;
            if (!FIRST) ld += g_ld[b];
            xc[T0] = nx0;
            xc[T1] = nx1;
            if (!LAST) {
                reinterpret_cast<float4*>(g_x)[b] =
                    make_float4(xc[0], xc[1], xc[2], xc[3]);
                g_ld[b] = ld;
            } else {
                float ss = xc[0] * xc[0] + xc[1] * xc[1] +
                           xc[2] * xc[2] + xc[3] * xc[3];
                out[b] = -0.5f * ss - 3.6757541328186907f + ld;
            }
        }
        buf ^= 1;
    }
}

extern "C" void kernel_launch(void* const* d_in, const int* in_sizes, int n_in,
                              void* d_out, int out_size)
{
    const float* theta = (const float*)d_in[0];
    const float* h     = (const float*)d_in[1];
    const float* sW1   = (const float*)d_in[2];
    const float* sb1   = (const float*)d_in[3];
    const float* sW2   = (const float*)d_in[4];
    const float* sb2   = (const float*)d_in[5];
    const float* sW3   = (const float*)d_in[6];
    const float* sb3   = (const float*)d_in[7];
    const float* tW1   = (const float*)d_in[8];
    const float* tb1   = (const float*)d_in[9];
    const float* tW2   = (const float*)d_in[10];
    const float* tb2   = (const float*)d_in[11];
    const float* tW3   = (const float*)d_in[12];
    const float* tb3   = (const float*)d_in[13];
    float* out = (float*)d_out;

    int nsm = 148;
    cudaDeviceGetAttribute(&nsm, cudaDevAttrMultiProcessorCount, 0);

    cudaFuncSetAttribute(nvp_layer<0>, cudaFuncAttributeMaxDynamicSharedMemorySize, SMEM_BYTES);
    cudaFuncSetAttribute(nvp_layer<1>, cudaFuncAttributeMaxDynamicSharedMemorySize, SMEM_BYTES);
    cudaFuncSetAttribute(nvp_layer<2>, cudaFuncAttributeMaxDynamicSharedMemorySize, SMEM_BYTES);
    cudaFuncSetAttribute(nvp_layer<3>, cudaFuncAttributeMaxDynamicSharedMemorySize, SMEM_BYTES);

    // pre-pass: h -> bf16 (BTOT*64 elems, 8 per thread, 256 threads/block)
    cvt_h_kernel<<<(BTOT * 64) / (8 * 256), 256>>>(h);

    dim3 grid(nsm), blk(NTHREADS);
    #define ARGS(L) theta, h,                                        \
        sW1 + (L) * 66 * 128, sb1 + (L) * 128,                       \
        sW2 + (L) * 128 * 128, sb2 + (L) * 128,                      \
        sW3 + (L) * 128 * 2, sb3 + (L) * 2,                          \
        tW1 + (L) * 66 * 128, tb1 + (L) * 128,                       \
        tW2 + (L) * 128 * 128, tb2 + (L) * 128,                      \
        tW3 + (L) * 128 * 2, tb3 + (L) * 2, out

    nvp_layer<0><<<grid, blk, SMEM_BYTES>>>(ARGS(0));
    nvp_layer<1><<<grid, blk, SMEM_BYTES>>>(ARGS(1));
    nvp_layer<2><<<grid, blk, SMEM_BYTES>>>(ARGS(2));
    nvp_layer<3><<<grid, blk, SMEM_BYTES>>>(ARGS(3));
    #undef ARGS
}